// round 16
// baseline (speedup 1.0000x reference)
#include <cuda_runtime.h>
#include <cuda_fp16.h>
#include <cstddef>
#include <cstdint>

#define H    400
#define CC   4
#define NN   16
#define OO   32
#define RR   4
#define HH   (H*H)          // 160000

// Static device scratch — T now fp16 (halves all T traffic)
__device__ __half g_T[(size_t)OO*CC*HH];   // 40.96 MB : T[o][c][i][j] fp16
__device__ float  g_XT[(size_t)NN*CC*HH];  // 40.96 MB : XT[n][c][j][k]
__device__ float  g_rows[NN*OO*H];
__device__ float  g_cols[NN*OO*H];

// ---- cp.async helpers ------------------------------------------------------
__device__ __forceinline__ void cp16(void* smem_dst, const void* gmem_src) {
    uint32_t d = (uint32_t)__cvta_generic_to_shared(smem_dst);
    asm volatile("cp.async.cg.shared.global [%0], [%1], 16;\n" :: "r"(d), "l"(gmem_src));
}
__device__ __forceinline__ void cp_commit() {
    asm volatile("cp.async.commit_group;\n");
}
template<int N>
__device__ __forceinline__ void cp_wait() {
    asm volatile("cp.async.wait_group %0;\n" :: "n"(N));
}
__device__ __forceinline__ float dot4(float4 a, float4 b) {
    return a.x*b.x + a.y*b.y + a.z*b.z + a.w*b.w;
}
// unpack 4 halves (one j-quad, stored as uint2) to float4
__device__ __forceinline__ float4 h4_to_f4(uint2 raw) {
    __half2 h0 = *reinterpret_cast<__half2*>(&raw.x);
    __half2 h1 = *reinterpret_cast<__half2*>(&raw.y);
    float2 f0 = __half22float2(h0);
    float2 f1 = __half22float2(h1);
    return make_float4(f0.x, f0.y, f1.x, f1.y);
}

// ---------------------------------------------------------------------------
// Kernel 1a: T[o,c,i,j] = sum_r L[o,c,i,r]*L[o,c,j,r], stored fp16.
// grid=(128,16), blk 256
// ---------------------------------------------------------------------------
__global__ __launch_bounds__(256)
void kT(const float* __restrict__ L, __half* __restrict__ T)
{
    const int s = blockIdx.x;                 // o*CC + c
    const float* Lp = L + (size_t)s * (H*RR);
    __half*      Tp = T + (size_t)s * HH;

    __shared__ float sL[H*RR];
    for (int idx = threadIdx.x; idx < H*RR; idx += 256) sL[idx] = Lp[idx];
    __syncthreads();

    const int base = blockIdx.y * 625;
    for (int loc = threadIdx.x; loc < 625; loc += 256) {
        const int item = base + loc;
        const int it = item / 100;
        const int jq = item % 100;
        const int i0 = it * 4, j0 = jq * 4;

        float4 li[4], lj[4];
        #pragma unroll
        for (int d = 0; d < 4; d++) {
            li[d] = *reinterpret_cast<const float4*>(&sL[(i0 + d) * 4]);
            lj[d] = *reinterpret_cast<const float4*>(&sL[(j0 + d) * 4]);
        }
        #pragma unroll
        for (int d = 0; d < 4; d++) {
            float4 v;
            v.x = dot4(li[d], lj[0]);
            v.y = dot4(li[d], lj[1]);
            v.z = dot4(li[d], lj[2]);
            v.w = dot4(li[d], lj[3]);
            union { __half2 h[2]; uint2 u; } pk;
            pk.h[0] = __floats2half2_rn(v.x, v.y);
            pk.h[1] = __floats2half2_rn(v.z, v.w);
            *reinterpret_cast<uint2*>(&Tp[(size_t)(i0 + d) * H + j0]) = pk.u;
        }
    }
}

// ---------------------------------------------------------------------------
// Kernel 1b: per-(n,c) transpose XT[j,k] = x[k,j].  grid=(13,13,64), blk 256 flat
// ---------------------------------------------------------------------------
__global__ __launch_bounds__(256)
void kTrans(const float* __restrict__ X, float* __restrict__ XT)
{
    __shared__ float t[32][33];
    const int s = blockIdx.z;
    const float* src = X  + (size_t)s * HH;
    float*       dst = XT + (size_t)s * HH;
    const int tx = threadIdx.x & 31;
    const int ty = threadIdx.x >> 5;

    const int j = blockIdx.x * 32 + tx;
    #pragma unroll
    for (int m = 0; m < 32; m += 8) {
        const int k = blockIdx.y * 32 + ty + m;
        if (k < H && j < H)
            t[ty + m][tx] = src[(size_t)k * H + j];
    }
    __syncthreads();
    const int k2 = blockIdx.y * 32 + tx;
    #pragma unroll
    for (int m = 0; m < 32; m += 8) {
        const int j2 = blockIdx.x * 32 + ty + m;
        if (j2 < H && k2 < H)
            dst[(size_t)j2 * H + k2] = t[tx][ty + m];
    }
}

// ---------------------------------------------------------------------------
// Kernel 2: FUSED marginals, T in fp16.  grid=(H,2), blk 256.
// stages: X[1024]f4 + XT[1024]f4 + T[1024]uint2 = 40 KB, x2 = 80 KB.
// ---------------------------------------------------------------------------
__global__ __launch_bounds__(256, 2)
void kMargF(const float* __restrict__ X, const float* __restrict__ XT,
            const __half* __restrict__ T,
            float* __restrict__ rowsOut, float* __restrict__ colsOut,
            const float* __restrict__ bias)
{
    extern __shared__ float sm[];
    float4* s4   = reinterpret_cast<float4*>(sm);          // [2][2048] f4 (X,XT)
    uint2*  sTu  = reinterpret_cast<uint2*>(sm + 16384);   // [2][1024] uint2 (T)

    const int i    = blockIdx.x;
    const int half = blockIdx.y;
    const int tid  = threadIdx.x;
    const int ks = tid & 15;
    const int tt = tid >> 4;
    const int nt = (tt & 3) * 4;
    const int ot = (tt >> 2) * 4;

    auto issue = [&](int ch) {
        const int q0 = ch * 16;
        const int full = (ch < 6);
        const int cq = full ? 16 : 4;
        float4* dX = s4 + (ch & 1) * 2048;
        float4* dY = dX + 1024;
        uint2*  dT = sTu + (ch & 1) * 1024;
        for (int idx = tid; idx < 64 * cq; idx += 256) {
            const int r  = full ? (idx >> 4) : (idx >> 2);
            const int q2 = full ? (idx & 15) : (idx & 3);
            const int c = r >> 4, m = r & 15;
            const size_t off = (((size_t)(m * 4 + c)) * H + i) * H + (q0 + q2) * 4;
            cp16(&dX[r * 16 + q2], &X [off]);
            cp16(&dY[r * 16 + q2], &XT[off]);
        }
        // T: 8 bytes per quad -> cp16 covers 2 quads
        const int units = full ? 8 : 2;
        for (int idx = tid; idx < 64 * units; idx += 256) {
            const int r = full ? (idx >> 3) : (idx >> 1);
            const int u = full ? (idx & 7)  : (idx & 1);
            const int c = r >> 4, m = r & 15;
            cp16(&dT[r * 16 + 2 * u],
                 &T[((((size_t)(half * 16 + m)) * CC + c) * H + i) * H + (q0 + 2 * u) * 4]);
        }
        cp_commit();
    };

    float accR[4][4] = {};
    float accC[4][4] = {};

    issue(0);
    #pragma unroll 1
    for (int ch = 0; ch < 7; ch++) {
        if (ch + 1 < 7) { issue(ch + 1); cp_wait<1>(); }
        else            { cp_wait<0>(); }
        __syncthreads();

        const int cq = (ch < 6) ? 16 : 4;
        const float4* bX = s4 + (ch & 1) * 2048;
        const float4* bY = bX + 1024;
        const uint2*  bT = sTu + (ch & 1) * 1024;
        if (ks < cq) {
            #pragma unroll
            for (int c = 0; c < 4; c++) {
                float4 tv[4], xv[4], yv[4];
                #pragma unroll
                for (int b = 0; b < 4; b++)
                    tv[b] = h4_to_f4(bT[(c * 16 + ot + b) * 16 + ks]);
                #pragma unroll
                for (int a = 0; a < 4; a++) xv[a] = bX[(c * 16 + nt + a) * 16 + ks];
                #pragma unroll
                for (int a = 0; a < 4; a++) yv[a] = bY[(c * 16 + nt + a) * 16 + ks];
                #pragma unroll
                for (int a = 0; a < 4; a++)
                    #pragma unroll
                    for (int b = 0; b < 4; b++) {
                        accR[a][b] += dot4(xv[a], tv[b]);
                        accC[a][b] += dot4(yv[a], tv[b]);
                    }
            }
        }
        __syncthreads();
    }

    float* red = sm;    // 4096 floats (reuse X stage region)
    const int tt2 = tid >> 4, ab = tid & 15;
    const int a2 = ab >> 2, b2 = ab & 3;
    const int n2  = (tt2 & 3) * 4 + a2;
    const int op2 = (tt2 >> 2) * 4 + b2;
    const int o2  = half * 16 + op2;

    #pragma unroll
    for (int a = 0; a < 4; a++)
        #pragma unroll
        for (int b = 0; b < 4; b++)
            red[(tt * 16 + a * 4 + b) * 16 + ks] = accR[a][b];
    __syncthreads();
    {
        float v = 0.f;
        #pragma unroll
        for (int s2 = 0; s2 < 16; s2++) v += red[tid * 16 + s2];
        v += bias[o2];
        rowsOut[((size_t)n2 * OO + o2) * H + i] = v;
    }
    __syncthreads();
    #pragma unroll
    for (int a = 0; a < 4; a++)
        #pragma unroll
        for (int b = 0; b < 4; b++)
            red[(tt * 16 + a * 4 + b) * 16 + ks] = accC[a][b];
    __syncthreads();
    {
        float v = 0.f;
        #pragma unroll
        for (int s2 = 0; s2 < 16; s2++) v += red[tid * 16 + s2];
        colsOut[((size_t)n2 * OO + o2) * H + i] = v;
    }
}

// ---------------------------------------------------------------------------
// Kernel 3: kOut — one block per i, all 32 o, 512 threads, T in fp16.
// grid=400, block 512.  thread = (n = tid>>5, q = tid&31).
// T stages: 8 stages of 64 rows x 32 quads x 8B = 16 KB each, 2-buffered.
// ---------------------------------------------------------------------------
__global__ __launch_bounds__(512, 2)
void kOut(const float* __restrict__ X, const __half* __restrict__ T,
          const float* __restrict__ rows, const float* __restrict__ cols,
          float* __restrict__ out)
{
    extern __shared__ float sm[];
    uint2* sTu = reinterpret_cast<uint2*>(sm);    // [2][2048] uint2 (T stages)
    float* sr  = sm + 8192;                       // 512 floats (rows, all n,o)

    const int i   = blockIdx.x;
    const int tid = threadIdx.x;

    {
        const int n = tid >> 5, o = tid & 31;
        sr[tid] = rows[((size_t)n * OO + o) * H + i];
    }

    // stage st = qc*2 + s : q-chunk qc (0..3), o-half s (0..1)
    auto issueT = [&](int st) {
        const int qc = st >> 1, s = st & 1;
        const int q0 = qc * 32;
        const int full = (qc < 3);
        uint2* dT = sTu + (st & 1) * 2048;
        const int units = full ? 16 : 2;   // cp16 = 2 quads
        for (int idx = tid; idx < 64 * units; idx += 512) {
            const int r = full ? (idx >> 4) : (idx >> 1);
            const int u = full ? (idx & 15) : (idx & 1);
            const int c = r >> 4, oo = r & 15;
            const int o = s * 16 + oo;
            cp16(&dT[r * 32 + 2 * u],
                 &T[(((size_t)o * CC + c) * H + i) * H + (q0 + 2 * u) * 4]);
        }
        cp_commit();
    };

    const int n = tid >> 5;      // one n per thread (0..15)
    const int q = tid & 31;      // quad lane

    float4 xv[4];

    issueT(0);
    #pragma unroll 1
    for (int st = 0; st < 8; st++) {
        if (st + 1 < 8) { issueT(st + 1); cp_wait<1>(); }
        else            { cp_wait<0>(); }
        __syncthreads();

        const int qc = st >> 1, s = st & 1;
        const int q0 = qc * 32;
        const int cq = (qc < 3) ? 32 : 4;
        const uint2* bT = sTu + (st & 1) * 2048;

        if (q < cq) {
            if (s == 0) {   // new q-chunk: load X once, reuse for both o-halves
                #pragma unroll
                for (int c = 0; c < 4; c++)
                    xv[c] = __ldg(reinterpret_cast<const float4*>(
                        &X[(((size_t)(n * 4 + c)) * H + i) * H + (q0 + q) * 4]));
            }
            #pragma unroll 4
            for (int oo = 0; oo < 16; oo++) {
                const int o = s * 16 + oo;
                float4 tv[4];
                #pragma unroll
                for (int c = 0; c < 4; c++)
                    tv[c] = h4_to_f4(bT[(c * 16 + oo) * 32 + q]);

                float4 cv = __ldg(reinterpret_cast<const float4*>(
                    &cols[((size_t)n * OO + o) * H + (q0 + q) * 4]));
                const float base = sr[n * 32 + o];
                float4 av;
                av.x = base + cv.x;
                av.y = base + cv.y;
                av.z = base + cv.z;
                av.w = base + cv.w;
                #pragma unroll
                for (int c = 0; c < 4; c++) {
                    av.x -= xv[c].x * tv[c].x;
                    av.y -= xv[c].y * tv[c].y;
                    av.z -= xv[c].z * tv[c].z;
                    av.w -= xv[c].w * tv[c].w;
                }
                *reinterpret_cast<float4*>(
                    &out[(((size_t)n * OO + o) * H + i) * H + (q0 + q) * 4]) = av;
            }
        }
        __syncthreads();
    }
}

// ---------------------------------------------------------------------------
extern "C" void kernel_launch(void* const* d_in, const int* in_sizes, int n_in,
                              void* d_out, int out_size)
{
    const float* x    = (const float*)d_in[0];
    const float* wL   = (const float*)d_in[1];
    const float* bias = (const float*)d_in[2];
    float*       out  = (float*)d_out;

    __half* Tbuf;
    float *XTbuf, *rowsBuf, *colsBuf;
    cudaGetSymbolAddress((void**)&Tbuf,    g_T);
    cudaGetSymbolAddress((void**)&XTbuf,   g_XT);
    cudaGetSymbolAddress((void**)&rowsBuf, g_rows);
    cudaGetSymbolAddress((void**)&colsBuf, g_cols);

    const int smMarg = 2 * 2048 * sizeof(float4) + 2 * 1024 * sizeof(uint2);  // 81920
    const int smOut  = 2 * 2048 * sizeof(uint2) + 512 * 4;                    // 34816
    cudaFuncSetAttribute(kMargF, cudaFuncAttributeMaxDynamicSharedMemorySize, smMarg);
    cudaFuncSetAttribute(kOut,   cudaFuncAttributeMaxDynamicSharedMemorySize, smOut);

    kT<<<dim3(OO * CC, 16), 256>>>(wL, Tbuf);
    kTrans<<<dim3(13, 13, NN * CC), 256>>>(x, XTbuf);

    kMargF<<<dim3(H, 2), 256, smMarg>>>(x, XTbuf, Tbuf, rowsBuf, colsBuf, bias);

    kOut<<<H, 512, smOut>>>(x, Tbuf, rowsBuf, colsBuf, out);
}

// round 17
// speedup vs baseline: 1.3325x; 1.3325x over previous
#include <cuda_runtime.h>
#include <cuda_fp16.h>
#include <cstddef>
#include <cstdint>

#define H    400
#define CC   4
#define NN   16
#define OO   32
#define RR   4
#define HH   (H*H)          // 160000

// Static device scratch — T in fp16 (halves all T DRAM traffic)
__device__ __half g_T[(size_t)OO*CC*HH];   // 40.96 MB : T[o][c][i][j] fp16
__device__ float  g_XT[(size_t)NN*CC*HH];  // 40.96 MB : XT[n][c][j][k]
__device__ float  g_rows[NN*OO*H];
__device__ float  g_cols[NN*OO*H];

// ---- cp.async helpers ------------------------------------------------------
__device__ __forceinline__ void cp16(void* smem_dst, const void* gmem_src) {
    uint32_t d = (uint32_t)__cvta_generic_to_shared(smem_dst);
    asm volatile("cp.async.cg.shared.global [%0], [%1], 16;\n" :: "r"(d), "l"(gmem_src));
}
__device__ __forceinline__ void cp_commit() {
    asm volatile("cp.async.commit_group;\n");
}
template<int N>
__device__ __forceinline__ void cp_wait() {
    asm volatile("cp.async.wait_group %0;\n" :: "n"(N));
}
__device__ __forceinline__ float dot4(float4 a, float4 b) {
    return a.x*b.x + a.y*b.y + a.z*b.z + a.w*b.w;
}
__device__ __forceinline__ float4 h4_to_f4(uint2 raw) {
    __half2 h0 = *reinterpret_cast<__half2*>(&raw.x);
    __half2 h1 = *reinterpret_cast<__half2*>(&raw.y);
    float2 f0 = __half22float2(h0);
    float2 f1 = __half22float2(h1);
    return make_float4(f0.x, f0.y, f1.x, f1.y);
}

// ---------------------------------------------------------------------------
// Kernel 1a: T[o,c,i,j] = sum_r L[o,c,i,r]*L[o,c,j,r], stored fp16.
// grid=(128,16), blk 256
// ---------------------------------------------------------------------------
__global__ __launch_bounds__(256)
void kT(const float* __restrict__ L, __half* __restrict__ T)
{
    const int s = blockIdx.x;                 // o*CC + c
    const float* Lp = L + (size_t)s * (H*RR);
    __half*      Tp = T + (size_t)s * HH;

    __shared__ float sL[H*RR];
    for (int idx = threadIdx.x; idx < H*RR; idx += 256) sL[idx] = Lp[idx];
    __syncthreads();

    const int base = blockIdx.y * 625;
    for (int loc = threadIdx.x; loc < 625; loc += 256) {
        const int item = base + loc;
        const int it = item / 100;
        const int jq = item % 100;
        const int i0 = it * 4, j0 = jq * 4;

        float4 li[4], lj[4];
        #pragma unroll
        for (int d = 0; d < 4; d++) {
            li[d] = *reinterpret_cast<const float4*>(&sL[(i0 + d) * 4]);
            lj[d] = *reinterpret_cast<const float4*>(&sL[(j0 + d) * 4]);
        }
        #pragma unroll
        for (int d = 0; d < 4; d++) {
            float4 v;
            v.x = dot4(li[d], lj[0]);
            v.y = dot4(li[d], lj[1]);
            v.z = dot4(li[d], lj[2]);
            v.w = dot4(li[d], lj[3]);
            union { __half2 h[2]; uint2 u; } pk;
            pk.h[0] = __floats2half2_rn(v.x, v.y);
            pk.h[1] = __floats2half2_rn(v.z, v.w);
            *reinterpret_cast<uint2*>(&Tp[(size_t)(i0 + d) * H + j0]) = pk.u;
        }
    }
}

// ---------------------------------------------------------------------------
// Kernel 1b: per-(n,c) transpose XT[j,k] = x[k,j].  grid=(13,13,64), blk 256 flat
// ---------------------------------------------------------------------------
__global__ __launch_bounds__(256)
void kTrans(const float* __restrict__ X, float* __restrict__ XT)
{
    __shared__ float t[32][33];
    const int s = blockIdx.z;
    const float* src = X  + (size_t)s * HH;
    float*       dst = XT + (size_t)s * HH;
    const int tx = threadIdx.x & 31;
    const int ty = threadIdx.x >> 5;

    const int j = blockIdx.x * 32 + tx;
    #pragma unroll
    for (int m = 0; m < 32; m += 8) {
        const int k = blockIdx.y * 32 + ty + m;
        if (k < H && j < H)
            t[ty + m][tx] = src[(size_t)k * H + j];
    }
    __syncthreads();
    const int k2 = blockIdx.y * 32 + tx;
    #pragma unroll
    for (int m = 0; m < 32; m += 8) {
        const int j2 = blockIdx.x * 32 + ty + m;
        if (j2 < H && k2 < H)
            dst[(size_t)j2 * H + k2] = t[tx][ty + m];
    }
}

// ---------------------------------------------------------------------------
// Kernel 2: FUSED marginals, T fp16 staged + converted ONCE to fp32 smem.
// grid=(H,2), blk 256.
// smem: X/XT [2][2048]f4 (64KB) + Th [2][1024]uint2 (16KB) + Tf [1024]f4 (16KB)
// ---------------------------------------------------------------------------
__global__ __launch_bounds__(256, 2)
void kMargF(const float* __restrict__ X, const float* __restrict__ XT,
            const __half* __restrict__ T,
            float* __restrict__ rowsOut, float* __restrict__ colsOut,
            const float* __restrict__ bias)
{
    extern __shared__ float sm[];
    float4* s4  = reinterpret_cast<float4*>(sm);           // [2][2048] f4 (X,XT)
    uint2*  sTh = reinterpret_cast<uint2*>(sm + 16384);    // [2][1024] uint2
    float4* sTf = reinterpret_cast<float4*>(sm + 20480);   // [1024] f4

    const int i    = blockIdx.x;
    const int half = blockIdx.y;
    const int tid  = threadIdx.x;
    const int ks = tid & 15;
    const int tt = tid >> 4;
    const int nt = (tt & 3) * 4;
    const int ot = (tt >> 2) * 4;

    auto issue = [&](int ch) {
        const int q0 = ch * 16;
        const int full = (ch < 6);
        const int cq = full ? 16 : 4;
        float4* dX = s4 + (ch & 1) * 2048;
        float4* dY = dX + 1024;
        uint2*  dT = sTh + (ch & 1) * 1024;
        for (int idx = tid; idx < 64 * cq; idx += 256) {
            const int r  = full ? (idx >> 4) : (idx >> 2);
            const int q2 = full ? (idx & 15) : (idx & 3);
            const int c = r >> 4, m = r & 15;
            const size_t off = (((size_t)(m * 4 + c)) * H + i) * H + (q0 + q2) * 4;
            cp16(&dX[r * 16 + q2], &X [off]);
            cp16(&dY[r * 16 + q2], &XT[off]);
        }
        const int units = full ? 8 : 2;    // cp16 = 2 quads of fp16
        for (int idx = tid; idx < 64 * units; idx += 256) {
            const int r = full ? (idx >> 3) : (idx >> 1);
            const int u = full ? (idx & 7)  : (idx & 1);
            const int c = r >> 4, m = r & 15;
            cp16(&dT[r * 16 + 2 * u],
                 &T[((((size_t)(half * 16 + m)) * CC + c) * H + i) * H + (q0 + 2 * u) * 4]);
        }
        cp_commit();
    };

    float accR[4][4] = {};
    float accC[4][4] = {};

    issue(0);
    #pragma unroll 1
    for (int ch = 0; ch < 7; ch++) {
        if (ch + 1 < 7) { issue(ch + 1); cp_wait<1>(); }
        else            { cp_wait<0>(); }
        __syncthreads();                       // fp16 stage + prior compute done

        const int cq = (ch < 6) ? 16 : 4;
        const uint2* bTh = sTh + (ch & 1) * 1024;
        // convert once per element: 64*cq quads / 256 threads
        for (int idx = tid; idx < 64 * cq; idx += 256) {
            const int r  = (cq == 16) ? (idx >> 4) : (idx >> 2);
            const int q2 = (cq == 16) ? (idx & 15) : (idx & 3);
            sTf[r * 16 + q2] = h4_to_f4(bTh[r * 16 + q2]);
        }
        __syncthreads();                       // sTf ready

        const float4* bX = s4 + (ch & 1) * 2048;
        const float4* bY = bX + 1024;
        if (ks < cq) {
            #pragma unroll
            for (int c = 0; c < 4; c++) {
                float4 tv[4], xv[4], yv[4];
                #pragma unroll
                for (int b = 0; b < 4; b++) tv[b] = sTf[(c * 16 + ot + b) * 16 + ks];
                #pragma unroll
                for (int a = 0; a < 4; a++) xv[a] = bX[(c * 16 + nt + a) * 16 + ks];
                #pragma unroll
                for (int a = 0; a < 4; a++) yv[a] = bY[(c * 16 + nt + a) * 16 + ks];
                #pragma unroll
                for (int a = 0; a < 4; a++)
                    #pragma unroll
                    for (int b = 0; b < 4; b++) {
                        accR[a][b] += dot4(xv[a], tv[b]);
                        accC[a][b] += dot4(yv[a], tv[b]);
                    }
            }
        }
        __syncthreads();                       // guard bX/bY vs next cp.async
    }

    float* red = sm;    // 4096 floats (reuse X stage region)
    const int tt2 = tid >> 4, ab = tid & 15;
    const int a2 = ab >> 2, b2 = ab & 3;
    const int n2  = (tt2 & 3) * 4 + a2;
    const int op2 = (tt2 >> 2) * 4 + b2;
    const int o2  = half * 16 + op2;

    #pragma unroll
    for (int a = 0; a < 4; a++)
        #pragma unroll
        for (int b = 0; b < 4; b++)
            red[(tt * 16 + a * 4 + b) * 16 + ks] = accR[a][b];
    __syncthreads();
    {
        float v = 0.f;
        #pragma unroll
        for (int s2 = 0; s2 < 16; s2++) v += red[tid * 16 + s2];
        v += bias[o2];
        rowsOut[((size_t)n2 * OO + o2) * H + i] = v;
    }
    __syncthreads();
    #pragma unroll
    for (int a = 0; a < 4; a++)
        #pragma unroll
        for (int b = 0; b < 4; b++)
            red[(tt * 16 + a * 4 + b) * 16 + ks] = accC[a][b];
    __syncthreads();
    {
        float v = 0.f;
        #pragma unroll
        for (int s2 = 0; s2 < 16; s2++) v += red[tid * 16 + s2];
        colsOut[((size_t)n2 * OO + o2) * H + i] = v;
    }
}

// ---------------------------------------------------------------------------
// Kernel 3: kOut — one block per i, all 32 o, 512 threads, T fp16 staged
// and converted ONCE per element into fp32 smem.
// smem: Th [2][2048]uint2 (32KB) + Tf [2048]f4 (32KB) + sr (2KB) = 66.5 KB.
// ---------------------------------------------------------------------------
__global__ __launch_bounds__(512, 2)
void kOut(const float* __restrict__ X, const __half* __restrict__ T,
          const float* __restrict__ rows, const float* __restrict__ cols,
          float* __restrict__ out)
{
    extern __shared__ float sm[];
    uint2*  sTh = reinterpret_cast<uint2*>(sm);            // [2][2048] uint2
    float4* sTf = reinterpret_cast<float4*>(sm + 8192);    // [2048] f4
    float*  sr  = sm + 16384;                              // 512 floats

    const int i   = blockIdx.x;
    const int tid = threadIdx.x;

    {
        const int n = tid >> 5, o = tid & 31;
        sr[tid] = rows[((size_t)n * OO + o) * H + i];
    }

    // stage st = qc*2 + s : q-chunk qc (0..3), o-half s (0..1)
    auto issueT = [&](int st) {
        const int qc = st >> 1, s = st & 1;
        const int q0 = qc * 32;
        const int full = (qc < 3);
        uint2* dT = sTh + (st & 1) * 2048;
        const int units = full ? 16 : 2;   // cp16 = 2 quads
        for (int idx = tid; idx < 64 * units; idx += 512) {
            const int r = full ? (idx >> 4) : (idx >> 1);
            const int u = full ? (idx & 15) : (idx & 1);
            const int c = r >> 4, oo = r & 15;
            const int o = s * 16 + oo;
            cp16(&dT[r * 32 + 2 * u],
                 &T[(((size_t)o * CC + c) * H + i) * H + (q0 + 2 * u) * 4]);
        }
        cp_commit();
    };

    const int n = tid >> 5;      // one n per thread (0..15)
    const int q = tid & 31;      // quad lane

    float4 xv[4];

    issueT(0);
    #pragma unroll 1
    for (int st = 0; st < 8; st++) {
        if (st + 1 < 8) { issueT(st + 1); cp_wait<1>(); }
        else            { cp_wait<0>(); }
        __syncthreads();                       // fp16 ready; prior sTf reads done

        const int qc = st >> 1, s = st & 1;
        const int q0 = qc * 32;
        const int cq = (qc < 3) ? 32 : 4;
        const uint2* bTh = sTh + (st & 1) * 2048;

        // convert once per element: 64*cq quads / 512 threads
        for (int idx = tid; idx < 64 * cq; idx += 512) {
            const int r  = (cq == 32) ? (idx >> 5) : (idx >> 2);
            const int q2 = (cq == 32) ? (idx & 31) : (idx & 3);
            sTf[r * 32 + q2] = h4_to_f4(bTh[r * 32 + q2]);
        }
        __syncthreads();                       // sTf ready

        if (q < cq) {
            if (s == 0) {   // new q-chunk: load X once, reuse for both o-halves
                #pragma unroll
                for (int c = 0; c < 4; c++)
                    xv[c] = __ldg(reinterpret_cast<const float4*>(
                        &X[(((size_t)(n * 4 + c)) * H + i) * H + (q0 + q) * 4]));
            }
            #pragma unroll 4
            for (int oo = 0; oo < 16; oo++) {
                const int o = s * 16 + oo;
                float4 tv[4];
                #pragma unroll
                for (int c = 0; c < 4; c++) tv[c] = sTf[(c * 16 + oo) * 32 + q];

                float4 cv = __ldg(reinterpret_cast<const float4*>(
                    &cols[((size_t)n * OO + o) * H + (q0 + q) * 4]));
                const float base = sr[n * 32 + o];
                float4 av;
                av.x = base + cv.x;
                av.y = base + cv.y;
                av.z = base + cv.z;
                av.w = base + cv.w;
                #pragma unroll
                for (int c = 0; c < 4; c++) {
                    av.x -= xv[c].x * tv[c].x;
                    av.y -= xv[c].y * tv[c].y;
                    av.z -= xv[c].z * tv[c].z;
                    av.w -= xv[c].w * tv[c].w;
                }
                *reinterpret_cast<float4*>(
                    &out[(((size_t)n * OO + o) * H + i) * H + (q0 + q) * 4]) = av;
            }
        }
    }
}

// ---------------------------------------------------------------------------
extern "C" void kernel_launch(void* const* d_in, const int* in_sizes, int n_in,
                              void* d_out, int out_size)
{
    const float* x    = (const float*)d_in[0];
    const float* wL   = (const float*)d_in[1];
    const float* bias = (const float*)d_in[2];
    float*       out  = (float*)d_out;

    __half* Tbuf;
    float *XTbuf, *rowsBuf, *colsBuf;
    cudaGetSymbolAddress((void**)&Tbuf,    g_T);
    cudaGetSymbolAddress((void**)&XTbuf,   g_XT);
    cudaGetSymbolAddress((void**)&rowsBuf, g_rows);
    cudaGetSymbolAddress((void**)&colsBuf, g_cols);

    const int smMarg = (16384 + 4096 + 4096) * sizeof(float);   // 98304
    const int smOut  = (8192 + 8192 + 512) * sizeof(float);     // 67584
    cudaFuncSetAttribute(kMargF, cudaFuncAttributeMaxDynamicSharedMemorySize, smMarg);
    cudaFuncSetAttribute(kOut,   cudaFuncAttributeMaxDynamicSharedMemorySize, smOut);

    kT<<<dim3(OO * CC, 16), 256>>>(wL, Tbuf);
    kTrans<<<dim3(13, 13, NN * CC), 256>>>(x, XTbuf);

    kMargF<<<dim3(H, 2), 256, smMarg>>>(x, XTbuf, Tbuf, rowsBuf, colsBuf, bias);

    kOut<<<H, 512, smOut>>>(x, Tbuf, rowsBuf, colsBuf, out);
}